// round 8
// baseline (speedup 1.0000x reference)
#include <cuda_runtime.h>
#include <cstdint>

// ---------------------------------------------------------------------------
// EdgeUpdate: fused gather + MLP(relu) + per-edge tensor-product contraction
// + residual + LayerNorm.  tf32 mma.sync, W2 streamed from L2.
// R7: 384 threads (3 warps/SMSP), 4 m-groups x 3-way kt split, 3-way smem
// accumulator reduction.  (tcgen05 unavailable: harness ptxas targets sm_103
// without the 'a' suffix.)
// ---------------------------------------------------------------------------

constexpr int H_STR  = 140;            // Hs row stride (4 groups * 34 + pad)
constexpr int W2_STR = 72;             // W2 chunk row stride (64 cols + pad)
constexpr int F_STR  = 81;             // feats row stride (80 + pad)

constexpr int HS_SZ   = 128 * H_STR;           // 17920 floats
constexpr int W2_SZ   = 136 * W2_STR;          // 9792 floats per buffer
constexpr int FS_OFF  = HS_SZ + 2 * W2_SZ;     // 37504
constexpr int FS_SZ   = 128 * F_STR;           // 10368
constexpr int B1_OFF  = FS_OFF + FS_SZ;        // 47872
constexpr int GB_OFF  = B1_OFF + 128;          // 48000
constexpr int SMEM_FLOATS = GB_OFF + 128;      // 48128 -> 192512 bytes

// tf32-rounded copies of W2 / b2 (written once by round_w2 pre-pass kernel)
__device__ float w2r[128 * 5120];
__device__ float b2r[5120];

__device__ __forceinline__ unsigned cvt_tf32(float x) {
    unsigned r;
    asm("cvt.rna.tf32.f32 %0, %1;" : "=r"(r) : "f"(x));
    return r;
}

__device__ __forceinline__ void mma_tf32(float* c, const unsigned* a, const unsigned* b) {
    asm volatile(
        "mma.sync.aligned.m16n8k8.row.col.f32.tf32.tf32.f32 "
        "{%0,%1,%2,%3}, {%4,%5,%6,%7}, {%8,%9}, {%0,%1,%2,%3};"
        : "+f"(c[0]), "+f"(c[1]), "+f"(c[2]), "+f"(c[3])
        : "r"(a[0]), "r"(a[1]), "r"(a[2]), "r"(a[3]), "r"(b[0]), "r"(b[1]));
}

__device__ __forceinline__ void cp_async16(float* smem_dst, const float* gsrc) {
    unsigned saddr = (unsigned)__cvta_generic_to_shared(smem_dst);
    asm volatile("cp.async.cg.shared.global [%0], [%1], 16;" :: "r"(saddr), "l"(gsrc));
}

__global__ void round_w2(const float* __restrict__ W2, const float* __restrict__ b2) {
    const int i = blockIdx.x * 256 + threadIdx.x;
    if (i < 128 * 5120) w2r[i] = __uint_as_float(cvt_tf32(W2[i]));
    if (i < 5120)       b2r[i] = __uint_as_float(cvt_tf32(b2[i]));
}

__global__ __launch_bounds__(384, 1)
void edge_kernel(const float* __restrict__ res,
                 const float* __restrict__ xf,
                 const float* __restrict__ esh,
                 const float* __restrict__ W1,
                 const float* __restrict__ b1,
                 const float* __restrict__ gamma,
                 const float* __restrict__ beta,
                 const int* __restrict__ ei,
                 float* __restrict__ out,
                 int E)
{
    extern __shared__ float smem[];
    const int tid   = threadIdx.x;
    const int lane  = tid & 31;
    const int w     = tid >> 5;        // warp 0..11
    const int mg    = w & 3;           // m-group 0..3 (32 rows each)
    const int kh    = w >> 2;          // kt-range third 0..2
    const int g     = lane >> 2;       // groupID 0..7
    const int q     = lane & 3;        // threadID_in_group 0..3
    const int e0    = blockIdx.x * 128;

    float* Hs   = smem;
    float* W2s0 = smem + HS_SZ;
    float* fs   = smem + FS_OFF;
    float* b1s  = smem + B1_OFF;
    float* gs   = smem + GB_OFF;
    float* bs   = gs + 64;

    // ---------------- phase 0: stage W1 / X / b1 / gamma / beta ------------
    float* W1s = W2s0;                 // 8192 floats (aliased into W2 buffers)
    float* Xs  = W2s0 + 8192;          // 128 x 65   (aliased)
    for (int idx = tid; idx < 8192; idx += 384) {
        W1s[idx] = W1[idx];
        int r = idx >> 6, c = idx & 63;
        Xs[r * 65 + c] = xf[(size_t)(e0 + r) * 64 + c];
    }
    if (tid < 128) b1s[tid] = b1[tid];
    if (tid < 64) { gs[tid] = gamma[tid]; bs[tid] = beta[tid]; }

    // ---------------- feats gather (one edge per thread, tid<128) ----------
    if (tid < 128) {
        const int e = e0 + tid;
        const int di = ei[e];            // dst = res[edge_index[0]]
        const int si = ei[E + e];        // src = res[edge_index[1]]
        const float* sr = res + (size_t)si * 56;
        const float* dr = res + (size_t)di * 56;
        const float s0 = esh[e * 4 + 0];
        const float sx = esh[e * 4 + 1];
        const float sy = esh[e * 4 + 2];
        const float sz = esh[e * 4 + 3];
        float* fr = fs + tid * F_STR;
        #pragma unroll
        for (int j = 0; j < 32; j++) { fr[j] = sr[j] * s0; fr[32 + j] = dr[j] * s0; }
        const float inv3 = 0.57735026918962576f;   // 1/sqrt(3)
        #pragma unroll
        for (int m = 0; m < 8; m++) {
            fr[64 + m] = (sr[32 + 3*m] * sx + sr[33 + 3*m] * sy + sr[34 + 3*m] * sz) * inv3;
            fr[72 + m] = (dr[32 + 3*m] * sx + dr[33 + 3*m] * sy + dr[34 + 3*m] * sz) * inv3;
        }
    }
    __syncthreads();

    // ---------------- phase 1: H = relu(X @ W1 + b1), rounded to tf32 ------
    // Permuted column layout for LDS.64 A loads:  col(k) = (k&3)*34 + (k>>2)
    if (tid < 256) {
        const int e    = tid >> 1;
        const int half = tid & 1;
        float* hrow = Hs + e * H_STR;
        #pragma unroll 1
        for (int jb = 0; jb < 2; jb++) {
            const int j0 = half * 64 + jb * 32;
            float acc[32];
            #pragma unroll
            for (int jj = 0; jj < 32; jj++) acc[jj] = b1s[j0 + jj];
            #pragma unroll 4
            for (int i = 0; i < 64; i++) {
                const float xv = Xs[e * 65 + i];
                const float* wrow = W1s + i * 128 + j0;
                #pragma unroll
                for (int jj = 0; jj < 32; jj++) acc[jj] = fmaf(xv, wrow[jj], acc[jj]);
            }
            #pragma unroll
            for (int jj = 0; jj < 32; jj++) {
                const int j = j0 + jj;
                hrow[(j & 3) * 34 + (j >> 2)] =
                    __uint_as_float(cvt_tf32(fmaxf(acc[jj], 0.f)));
            }
        }
    }
    if (tid < 128) {   // augmented column (b2) + K-padding, permuted slots
        float* hrow = Hs + tid * H_STR;
        hrow[32] = 1.0f;                            // k=128
        hrow[33] = 0.f; hrow[66] = 0.f; hrow[67] = 0.f;
        hrow[100] = 0.f; hrow[101] = 0.f; hrow[134] = 0.f; hrow[135] = 0.f;
    }
    __syncthreads();   // Xs / W1s dead from here; W2 buffers take over

    // zero K-padding rows (129..135) of both W2 chunk buffers
    for (int idx = tid; idx < 7 * W2_STR * 2; idx += 384) {
        int bsel = idx / (7 * W2_STR);
        int rr   = idx % (7 * W2_STR);
        W2s0[bsel * W2_SZ + 129 * W2_STR + rr] = 0.f;
    }

    // ---------------- main loop: 80 d-chunks of (pre-rounded) W2 -----------
    auto prefetch = [&](int d, int buf) {
        float* dstb = W2s0 + buf * W2_SZ;
        const float* src_base = w2r + (size_t)d * 64;
        #pragma unroll 2
        for (int c = tid; c < 128 * 16; c += 384) {
            int k = c >> 4, seg = c & 15;
            cp_async16(dstb + k * W2_STR + seg * 4, src_base + (size_t)k * 5120 + seg * 4);
        }
        if (tid < 16) cp_async16(dstb + 128 * W2_STR + tid * 4, b2r + (size_t)d * 64 + tid * 4);
        asm volatile("cp.async.commit_group;");
    };

    prefetch(0, 0);

    float acc[2][8][4];
    #pragma unroll
    for (int mt = 0; mt < 2; mt++)
        #pragma unroll
        for (int nt = 0; nt < 8; nt++)
            #pragma unroll
            for (int i = 0; i < 4; i++) acc[mt][nt][i] = 0.f;

    const int rowA0    = mg * 32 + g;       // a0/a2 row of m-tile 0
    const int kt_begin = kh * 6;            // 0 / 6 / 12
    const int kt_end   = (kh == 2) ? 17 : kt_begin + 6;

    const float* hb0 = Hs + (rowA0)      * H_STR + q * 34;
    const float* hb1 = Hs + (rowA0 + 8)  * H_STR + q * 34;
    const float* hb2 = Hs + (rowA0 + 16) * H_STR + q * 34;
    const float* hb3 = Hs + (rowA0 + 24) * H_STR + q * 34;

    #pragma unroll 1
    for (int d = 0; d < 80; d++) {
        const int buf = d & 1;
        if (d + 1 < 80) {
            prefetch(d + 1, buf ^ 1);
            asm volatile("cp.async.wait_group 1;");
        } else {
            asm volatile("cp.async.wait_group 0;");
        }
        __syncthreads();

        const float* Wb = W2s0 + buf * W2_SZ;
        const float f00 = fs[(rowA0)      * F_STR + d];
        const float f01 = fs[(rowA0 + 8)  * F_STR + d];
        const float f10 = fs[(rowA0 + 16) * F_STR + d];
        const float f11 = fs[(rowA0 + 24) * F_STR + d];

        #pragma unroll 3
        for (int kt = kt_begin; kt < kt_end; kt++) {
            const int k0 = kt * 8 + q;
            // A: one LDS.64 per row pair (k0, k0+4) thanks to permuted layout
            const float2 ha0 = *(const float2*)(hb0 + 2 * kt);
            const float2 ha1 = *(const float2*)(hb1 + 2 * kt);
            const float2 ha2 = *(const float2*)(hb2 + 2 * kt);
            const float2 ha3 = *(const float2*)(hb3 + 2 * kt);
            unsigned a0[4], a1[4];
            a0[0] = __float_as_uint(ha0.x * f00); a0[2] = __float_as_uint(ha0.y * f00);
            a0[1] = __float_as_uint(ha1.x * f01); a0[3] = __float_as_uint(ha1.y * f01);
            a1[0] = __float_as_uint(ha2.x * f10); a1[2] = __float_as_uint(ha2.y * f10);
            a1[1] = __float_as_uint(ha3.x * f11); a1[3] = __float_as_uint(ha3.y * f11);
            const float* wk0 = Wb + (size_t)k0 * W2_STR;        // b0 rows (k)
            const float* wk1 = Wb + (size_t)(k0 + 4) * W2_STR;  // b1 rows (k+4)
            #pragma unroll
            for (int nt = 0; nt < 8; nt++) {
                unsigned b[2];
                b[0] = __float_as_uint(wk0[nt * 8 + g]);
                b[1] = __float_as_uint(wk1[nt * 8 + g]);
                mma_tf32(acc[0][nt], a0, b);
                mma_tf32(acc[1][nt], a1, b);
            }
        }
        __syncthreads();   // protect buf^1 before next prefetch overwrites it
    }

    // ---------------- cross-warp (3-way kt-split) accumulator reduction ----
    float* red = W2s0;                       // W2 buffers are dead now
    if (kh >= 1) {
        float* dst = red + (kh - 1) * 8192 + mg * 2048;
        #pragma unroll
        for (int mt = 0; mt < 2; mt++)
            #pragma unroll
            for (int nt = 0; nt < 8; nt++)
                #pragma unroll
                for (int i = 0; i < 4; i++)
                    dst[(mt * 32 + nt * 4 + i) * 32 + lane] = acc[mt][nt][i];
    }
    __syncthreads();
    if (kh == 0) {
        const float* s1 = red + mg * 2048;
        const float* s2 = red + 8192 + mg * 2048;
        #pragma unroll
        for (int mt = 0; mt < 2; mt++)
            #pragma unroll
            for (int nt = 0; nt < 8; nt++)
                #pragma unroll
                for (int i = 0; i < 4; i++) {
                    const int off = (mt * 32 + nt * 4 + i) * 32 + lane;
                    acc[mt][nt][i] += s1[off] + s2[off];
                }

        // ---------------- epilogue: residual + LayerNorm -------------------
        const float inv_s80 = 0.111803398874989485f;   // 1/sqrt(80)
        #pragma unroll
        for (int mt = 0; mt < 2; mt++) {
            #pragma unroll
            for (int par = 0; par < 2; par++) {
                const int r = rowA0 + mt * 16 + par * 8;
                const size_t rg = (size_t)(e0 + r);
                const float* xrow = xf + rg * 64;
                float v[16];
                float s = 0.f, ss = 0.f;
                #pragma unroll
                for (int nt = 0; nt < 8; nt++) {
                    const int h = nt * 8 + 2 * q;
                    const float2 xv = *(const float2*)(xrow + h);
                    const float v0 = acc[mt][nt][par * 2 + 0] * inv_s80 + xv.x;
                    const float v1 = acc[mt][nt][par * 2 + 1] * inv_s80 + xv.y;
                    v[nt * 2] = v0; v[nt * 2 + 1] = v1;
                    s += v0 + v1;
                    ss += v0 * v0 + v1 * v1;
                }
                s  += __shfl_xor_sync(0xffffffffu, s, 1);
                s  += __shfl_xor_sync(0xffffffffu, s, 2);
                ss += __shfl_xor_sync(0xffffffffu, ss, 1);
                ss += __shfl_xor_sync(0xffffffffu, ss, 2);
                const float mean = s * (1.f / 64.f);
                const float var  = ss * (1.f / 64.f) - mean * mean;
                const float rstd = rsqrtf(var + 1e-5f);
                float* orow = out + rg * 64;
                #pragma unroll
                for (int nt = 0; nt < 8; nt++) {
                    const int h = nt * 8 + 2 * q;
                    float2 o;
                    o.x = (v[nt * 2]     - mean) * rstd * gs[h]     + bs[h];
                    o.y = (v[nt * 2 + 1] - mean) * rstd * gs[h + 1] + bs[h + 1];
                    *(float2*)(orow + h) = o;
                }
            }
        }
    }
}

extern "C" void kernel_launch(void* const* d_in, const int* in_sizes, int n_in,
                              void* d_out, int out_size)
{
    const float* res   = (const float*)d_in[0];
    const float* xf    = (const float*)d_in[1];
    const float* esh   = (const float*)d_in[2];
    const float* W1    = (const float*)d_in[3];
    const float* b1    = (const float*)d_in[4];
    const float* W2    = (const float*)d_in[5];
    const float* b2    = (const float*)d_in[6];
    const float* gamma = (const float*)d_in[7];
    const float* beta  = (const float*)d_in[8];
    const int*   ei    = (const int*)d_in[9];   // int32: JAX x64-disabled

    const int E = in_sizes[1] / 64;            // edge_features is (E, 64)
    const size_t smem_bytes = SMEM_FLOATS * sizeof(float);

    cudaFuncSetAttribute(edge_kernel, cudaFuncAttributeMaxDynamicSharedMemorySize,
                         (int)smem_bytes);

    round_w2<<<(128 * 5120 + 255) / 256, 256>>>(W2, b2);
    edge_kernel<<<E / 128, 384, smem_bytes>>>(res, xf, esh, W1, b1,
                                              gamma, beta, ei, (float*)d_out, E);
}

// round 9
// speedup vs baseline: 1.7731x; 1.7731x over previous
#include <cuda_runtime.h>
#include <cuda_fp16.h>
#include <cstdint>

// ---------------------------------------------------------------------------
// EdgeUpdate: fused gather + MLP(relu) + per-edge tensor-product contraction
// + residual + LayerNorm.
// R8: fp16 mma.sync m16n8k16 (same 10-bit mantissa as tf32, 2x rate, half the
// bytes).  A (H) fragments persistent in registers; feats applied post-GEMM in
// fp32 (G = H@W2_d, acc += f*G).  W2 pre-packed to k-pair-interleaved fp16 by
// a pre-pass kernel; 4-deep cp.async ring, ONE __syncthreads per d-chunk.
// ---------------------------------------------------------------------------

constexpr int AP_W   = 0;       constexpr int AP_STR = 76;   // 128 x 76 u32
constexpr int BP_W   = 9728;    constexpr int BP_BUF = 5184; // 4 bufs x 72*72
constexpr int BP_STR = 72;
constexpr int W1_W   = 30464;                                // 8192 floats
constexpr int FS_W   = 38656;   constexpr int F_STR  = 81;   // 128 x 81
constexpr int B1_W   = 49024;
constexpr int GB_W   = 49152;
constexpr int SMEM_W = 49280;                                // 197120 bytes

// k-pair-packed fp16 W2aug chunks: w2h[d][kp][n], kp=0..71 (k=2kp,2kp+1)
__device__ unsigned w2h[80 * 72 * 64];

__device__ __forceinline__ void mma_f16(float* c, const unsigned* a,
                                        unsigned b0, unsigned b1) {
    asm volatile(
        "mma.sync.aligned.m16n8k16.row.col.f32.f16.f16.f32 "
        "{%0,%1,%2,%3}, {%4,%5,%6,%7}, {%8,%9}, {%0,%1,%2,%3};"
        : "+f"(c[0]), "+f"(c[1]), "+f"(c[2]), "+f"(c[3])
        : "r"(a[0]), "r"(a[1]), "r"(a[2]), "r"(a[3]), "r"(b0), "r"(b1));
}

__device__ __forceinline__ void mma_f16_z(float* d, const unsigned* a,
                                          unsigned b0, unsigned b1) {
    asm volatile(
        "mma.sync.aligned.m16n8k16.row.col.f32.f16.f16.f32 "
        "{%0,%1,%2,%3}, {%4,%5,%6,%7}, {%8,%9}, {%10,%11,%12,%13};"
        : "=f"(d[0]), "=f"(d[1]), "=f"(d[2]), "=f"(d[3])
        : "r"(a[0]), "r"(a[1]), "r"(a[2]), "r"(a[3]), "r"(b0), "r"(b1),
          "f"(0.f), "f"(0.f), "f"(0.f), "f"(0.f));
}

__device__ __forceinline__ void cp_async16(void* smem_dst, const void* gsrc) {
    unsigned saddr = (unsigned)__cvta_generic_to_shared(smem_dst);
    asm volatile("cp.async.cg.shared.global [%0], [%1], 16;" :: "r"(saddr), "l"(gsrc));
}

__global__ void pack_w2(const float* __restrict__ W2, const float* __restrict__ b2) {
    const int i = blockIdx.x * 256 + threadIdx.x;
    if (i >= 80 * 72 * 64) return;
    const int n  = i & 63;
    const int kp = (i >> 6) % 72;
    const int d  = i / (72 * 64);
    const int col = d * 64 + n;
    const int k0 = 2 * kp, k1 = 2 * kp + 1;
    const float lo = (k0 < 128) ? W2[(size_t)k0 * 5120 + col] : (k0 == 128 ? b2[col] : 0.f);
    const float hi = (k1 < 128) ? W2[(size_t)k1 * 5120 + col] : (k1 == 128 ? b2[col] : 0.f);
    __half2 h = __floats2half2_rn(lo, hi);
    w2h[(size_t)d * 4608 + kp * 64 + n] = *reinterpret_cast<unsigned*>(&h);
}

__global__ __launch_bounds__(256, 1)
void edge_kernel(const float* __restrict__ res,
                 const float* __restrict__ xf,
                 const float* __restrict__ esh,
                 const float* __restrict__ W1,
                 const float* __restrict__ b1,
                 const float* __restrict__ gamma,
                 const float* __restrict__ beta,
                 const int* __restrict__ ei,
                 float* __restrict__ out,
                 int E)
{
    extern __shared__ float smem[];
    unsigned* APu = (unsigned*)smem;            // k-pair-packed fp16 H
    unsigned* BPu = (unsigned*)(smem + BP_W);   // 4 W2-chunk buffers
    float*    W1s = smem + W1_W;
    float*    fs  = smem + FS_W;
    float*    b1s = smem + B1_W;
    float*    gs  = smem + GB_W;
    float*    bs  = gs + 64;

    const int tid  = threadIdx.x;
    const int lane = tid & 31;
    const int w    = tid >> 5;        // warp 0..7
    const int mg   = w & 3;           // m-group (32 rows)
    const int kh   = w >> 2;          // k-split half (0: ks 0..4, 1: ks 5..8)
    const int g    = lane >> 2;
    const int q    = lane & 3;
    const int e0   = blockIdx.x * 128;

    // ---- kick off first two W2-chunk prefetches immediately ----------------
    auto prefetch = [&](int d) {
        unsigned* dstb = BPu + (d & 3) * BP_BUF;
        const unsigned* src = w2h + (size_t)d * 4608;
        #pragma unroll
        for (int c = tid; c < 1152; c += 256) {
            const int kp = c >> 4, seg = c & 15;
            cp_async16(dstb + kp * BP_STR + seg * 4, src + c * 4);
        }
        asm volatile("cp.async.commit_group;");
    };
    prefetch(0);
    prefetch(1);

    // ---- stage W1 / b1 / gamma / beta --------------------------------------
    for (int idx = tid; idx < 8192; idx += 256) W1s[idx] = W1[idx];
    if (tid < 128) b1s[tid] = b1[tid];
    if (tid < 64) { gs[tid] = gamma[tid]; bs[tid] = beta[tid]; }

    // ---- feats gather (one edge per thread, tid<128) -----------------------
    if (tid < 128) {
        const int e  = e0 + tid;
        const int di = ei[e];
        const int si = ei[E + e];
        const float* sr = res + (size_t)si * 56;
        const float* dr = res + (size_t)di * 56;
        const float s0 = esh[e * 4 + 0];
        const float sx = esh[e * 4 + 1];
        const float sy = esh[e * 4 + 2];
        const float sz = esh[e * 4 + 3];
        float* fr = fs + tid * F_STR;
        #pragma unroll
        for (int j = 0; j < 32; j++) { fr[j] = sr[j] * s0; fr[32 + j] = dr[j] * s0; }
        const float inv3 = 0.57735026918962576f;   // 1/sqrt(3)
        #pragma unroll
        for (int m = 0; m < 8; m++) {
            fr[64 + m] = (sr[32 + 3*m] * sx + sr[33 + 3*m] * sy + sr[34 + 3*m] * sz) * inv3;
            fr[72 + m] = (dr[32 + 3*m] * sx + dr[33 + 3*m] * sy + dr[34 + 3*m] * sz) * inv3;
        }
    }
    __syncthreads();

    // ---- phase 1: H = relu(X @ W1 + b1) -> Ap (k-pair fp16) ----------------
    {
        const int e = tid >> 1, half = tid & 1;
        float x[64];
        const float4* xr = (const float4*)(xf + (size_t)(e0 + e) * 64);
        #pragma unroll
        for (int i = 0; i < 16; i++) {
            float4 v = xr[i];
            x[4*i] = v.x; x[4*i+1] = v.y; x[4*i+2] = v.z; x[4*i+3] = v.w;
        }
        #pragma unroll 1
        for (int jb = 0; jb < 2; jb++) {
            const int j0 = half * 64 + jb * 32;
            float acc2[32];
            #pragma unroll
            for (int jj = 0; jj < 32; jj++) acc2[jj] = b1s[j0 + jj];
            #pragma unroll
            for (int i = 0; i < 64; i++) {
                const float* wrow = W1s + i * 128 + j0;
                #pragma unroll
                for (int jj = 0; jj < 32; jj++) acc2[jj] = fmaf(x[i], wrow[jj], acc2[jj]);
            }
            #pragma unroll
            for (int jj = 0; jj < 32; jj += 2) {
                __half2 hv = __floats2half2_rn(fmaxf(acc2[jj],     0.f),
                                               fmaxf(acc2[jj + 1], 0.f));
                APu[e * AP_STR + half * 32 + jb * 16 + (jj >> 1)] =
                    *reinterpret_cast<unsigned*>(&hv);
            }
        }
    }
    if (tid < 128) {     // augmented cols: kp64 = (1,0) for b2 row; kp65..71 = 0
        APu[tid * AP_STR + 64] = 0x00003C00u;
        #pragma unroll
        for (int kp = 65; kp < 72; kp++) APu[tid * AP_STR + kp] = 0u;
    }
    __syncthreads();

    // ---- load persistent A fragments (H, unscaled) -------------------------
    const int cnt      = kh ? 4 : 5;
    const int kt_begin = kh * 5;
    const int rb0      = mg * 32;

    unsigned afr[2][5][4];
    #pragma unroll
    for (int mt = 0; mt < 2; mt++)
        #pragma unroll
        for (int ks = 0; ks < 5; ks++) {
            afr[mt][ks][0] = afr[mt][ks][1] = afr[mt][ks][2] = afr[mt][ks][3] = 0u;
            if (ks < cnt) {
                const int K8 = (kt_begin + ks) * 8;
                const int r0 = rb0 + mt * 16;
                afr[mt][ks][0] = APu[(r0 + g)     * AP_STR + K8 + q];
                afr[mt][ks][1] = APu[(r0 + 8 + g) * AP_STR + K8 + q];
                afr[mt][ks][2] = APu[(r0 + g)     * AP_STR + K8 + 4 + q];
                afr[mt][ks][3] = APu[(r0 + 8 + g) * AP_STR + K8 + 4 + q];
            }
        }

    float acc[2][8][4];
    #pragma unroll
    for (int mt = 0; mt < 2; mt++)
        #pragma unroll
        for (int nt = 0; nt < 8; nt++)
            #pragma unroll
            for (int i = 0; i < 4; i++) acc[mt][nt][i] = 0.f;

    const int rowA0 = rb0 + g;

    // ---- main loop: 80 d-chunks, one __syncthreads each --------------------
    #pragma unroll 1
    for (int d = 0; d < 80; d++) {
        if (d < 78) {
            prefetch(d + 2);
            asm volatile("cp.async.wait_group 2;");
        } else if (d == 78) {
            asm volatile("cp.async.wait_group 1;");
        } else {
            asm volatile("cp.async.wait_group 0;");
        }
        __syncthreads();

        const unsigned* Bb = BPu + (d & 3) * BP_BUF;
        float G[2][8][4];

        #pragma unroll
        for (int ks = 0; ks < 5; ks++) {
            if (ks < cnt) {
                const int K8 = (kt_begin + ks) * 8;
                const unsigned* br0 = Bb + (K8 + q)     * BP_STR + g;
                const unsigned* br1 = Bb + (K8 + 4 + q) * BP_STR + g;
                #pragma unroll
                for (int nt = 0; nt < 8; nt++) {
                    const unsigned b0 = br0[nt * 8];
                    const unsigned b1 = br1[nt * 8];
                    if (ks == 0) {
                        mma_f16_z(G[0][nt], afr[0][0], b0, b1);
                        mma_f16_z(G[1][nt], afr[1][0], b0, b1);
                    } else {
                        mma_f16(G[0][nt], afr[0][ks], b0, b1);
                        mma_f16(G[1][nt], afr[1][ks], b0, b1);
                    }
                }
            }
        }

        const float f00 = fs[(rowA0)      * F_STR + d];
        const float f01 = fs[(rowA0 + 8)  * F_STR + d];
        const float f10 = fs[(rowA0 + 16) * F_STR + d];
        const float f11 = fs[(rowA0 + 24) * F_STR + d];
        #pragma unroll
        for (int nt = 0; nt < 8; nt++) {
            acc[0][nt][0] = fmaf(f00, G[0][nt][0], acc[0][nt][0]);
            acc[0][nt][1] = fmaf(f00, G[0][nt][1], acc[0][nt][1]);
            acc[0][nt][2] = fmaf(f01, G[0][nt][2], acc[0][nt][2]);
            acc[0][nt][3] = fmaf(f01, G[0][nt][3], acc[0][nt][3]);
            acc[1][nt][0] = fmaf(f10, G[1][nt][0], acc[1][nt][0]);
            acc[1][nt][1] = fmaf(f10, G[1][nt][1], acc[1][nt][1]);
            acc[1][nt][2] = fmaf(f11, G[1][nt][2], acc[1][nt][2]);
            acc[1][nt][3] = fmaf(f11, G[1][nt][3], acc[1][nt][3]);
        }
    }
    __syncthreads();

    // ---- cross-warp (k-split) reduction ------------------------------------
    float* red = (float*)BPu;                    // chunk buffers dead
    if (kh == 1) {
        float* dst = red + mg * 2048;
        #pragma unroll
        for (int mt = 0; mt < 2; mt++)
            #pragma unroll
            for (int nt = 0; nt < 8; nt++)
                #pragma unroll
                for (int i = 0; i < 4; i++)
                    dst[(mt * 32 + nt * 4 + i) * 32 + lane] = acc[mt][nt][i];
    }
    __syncthreads();
    if (kh == 0) {
        const float* s1 = red + mg * 2048;
        #pragma unroll
        for (int mt = 0; mt < 2; mt++)
            #pragma unroll
            for (int nt = 0; nt < 8; nt++)
                #pragma unroll
                for (int i = 0; i < 4; i++)
                    acc[mt][nt][i] += s1[(mt * 32 + nt * 4 + i) * 32 + lane];

        // ---- epilogue: residual + LayerNorm --------------------------------
        const float inv_s80 = 0.111803398874989485f;   // 1/sqrt(80)
        #pragma unroll
        for (int mt = 0; mt < 2; mt++) {
            #pragma unroll
            for (int par = 0; par < 2; par++) {
                const int r = rowA0 + mt * 16 + par * 8;
                const size_t rg = (size_t)(e0 + r);
                const float* xrow = xf + rg * 64;
                float v[16];
                float s = 0.f, ss = 0.f;
                #pragma unroll
                for (int nt = 0; nt < 8; nt++) {
                    const int h = nt * 8 + 2 * q;
                    const float2 xv = *(const float2*)(xrow + h);
                    const float v0 = acc[mt][nt][par * 2 + 0] * inv_s80 + xv.x;
                    const float v1 = acc[mt][nt][par * 2 + 1] * inv_s80 + xv.y;
                    v[nt * 2] = v0; v[nt * 2 + 1] = v1;
                    s += v0 + v1;
                    ss += v0 * v0 + v1 * v1;
                }
                s  += __shfl_xor_sync(0xffffffffu, s, 1);
                s  += __shfl_xor_sync(0xffffffffu, s, 2);
                ss += __shfl_xor_sync(0xffffffffu, ss, 1);
                ss += __shfl_xor_sync(0xffffffffu, ss, 2);
                const float mean = s * (1.f / 64.f);
                const float var  = ss * (1.f / 64.f) - mean * mean;
                const float rstd = rsqrtf(var + 1e-5f);
                float* orow = out + rg * 64;
                #pragma unroll
                for (int nt = 0; nt < 8; nt++) {
                    const int h = nt * 8 + 2 * q;
                    float2 o;
                    o.x = (v[nt * 2]     - mean) * rstd * gs[h]     + bs[h];
                    o.y = (v[nt * 2 + 1] - mean) * rstd * gs[h + 1] + bs[h + 1];
                    *(float2*)(orow + h) = o;
                }
            }
        }
    }
}

extern "C" void kernel_launch(void* const* d_in, const int* in_sizes, int n_in,
                              void* d_out, int out_size)
{
    const float* res   = (const float*)d_in[0];
    const float* xf    = (const float*)d_in[1];
    const float* esh   = (const float*)d_in[2];
    const float* W1    = (const float*)d_in[3];
    const float* b1    = (const float*)d_in[4];
    const float* W2    = (const float*)d_in[5];
    const float* b2    = (const float*)d_in[6];
    const float* gamma = (const float*)d_in[7];
    const float* beta  = (const float*)d_in[8];
    const int*   ei    = (const int*)d_in[9];   // int32: JAX x64-disabled

    const int E = in_sizes[1] / 64;             // edge_features is (E, 64)
    const size_t smem_bytes = SMEM_W * sizeof(float);

    cudaFuncSetAttribute(edge_kernel, cudaFuncAttributeMaxDynamicSharedMemorySize,
                         (int)smem_bytes);

    pack_w2<<<(80 * 72 * 64 + 255) / 256, 256>>>(W2, b2);
    edge_kernel<<<E / 128, 256, smem_bytes>>>(res, xf, esh, W1, b1,
                                              gamma, beta, ei, (float*)d_out, E);
}

// round 11
// speedup vs baseline: 2.0580x; 1.1607x over previous
#include <cuda_runtime.h>
#include <cuda_fp16.h>
#include <cstdint>

// ---------------------------------------------------------------------------
// EdgeUpdate, R9.
//   fp16 mma.sync m16n8k16 everywhere (phase-1 MLP GEMM *and* big W2 GEMM).
//   384 threads: main loop = 4 m-groups x 3-way k-split, per-nt G reorder
//   (G transient 8 floats), feats applied post-GEMM in fp32.
//   Phase-1: X,W1 packed to k-pair fp16 in smem, 8 warps, C-frag pairs packed
//   straight into the A (H) k-pair layout.
//   W2 pre-packed fp16 (pack_w2); 4-deep cp.async ring, 1 syncthreads / d.
// ---------------------------------------------------------------------------

constexpr int AP_STR  = 76;                 // APu: 128 x 76 u32 (kp 0..71)
constexpr int BP_W    = 9728;               // u32 offset of B ring
constexpr int BP_BUF  = 5184;               // 72*72 u32 per buffer
constexpr int BP_STR  = 72;
constexpr int W1H_STR = 136;                // w1h row stride (conflict-free)
constexpr int XP_STR  = 36;                 // Xp row stride (conflict-free)
constexpr int FS_W    = 30464;  constexpr int F_STR = 81;   // 128 x 81 floats
constexpr int B1_W    = 40832;
constexpr int GB_W    = 40960;
constexpr int SMEM_W  = 41088;              // 164352 bytes

// k-pair-packed fp16 W2aug chunks: w2h[d][kp][n], kp=0..71 (k=2kp,2kp+1)
__device__ unsigned w2h[80 * 72 * 64];

__device__ __forceinline__ void mma_f16(float* c, const unsigned* a,
                                        unsigned b0, unsigned b1) {
    asm volatile(
        "mma.sync.aligned.m16n8k16.row.col.f32.f16.f16.f32 "
        "{%0,%1,%2,%3}, {%4,%5,%6,%7}, {%8,%9}, {%0,%1,%2,%3};"
        : "+f"(c[0]), "+f"(c[1]), "+f"(c[2]), "+f"(c[3])
        : "r"(a[0]), "r"(a[1]), "r"(a[2]), "r"(a[3]), "r"(b0), "r"(b1));
}

__device__ __forceinline__ void mma_f16_z(float* d, const unsigned* a,
                                          unsigned b0, unsigned b1) {
    asm volatile(
        "mma.sync.aligned.m16n8k16.row.col.f32.f16.f16.f32 "
        "{%0,%1,%2,%3}, {%4,%5,%6,%7}, {%8,%9}, {%10,%11,%12,%13};"
        : "=f"(d[0]), "=f"(d[1]), "=f"(d[2]), "=f"(d[3])
        : "r"(a[0]), "r"(a[1]), "r"(a[2]), "r"(a[3]), "r"(b0), "r"(b1),
          "f"(0.f), "f"(0.f), "f"(0.f), "f"(0.f));
}

__device__ __forceinline__ void cp_async16(void* smem_dst, const void* gsrc) {
    unsigned saddr = (unsigned)__cvta_generic_to_shared(smem_dst);
    asm volatile("cp.async.cg.shared.global [%0], [%1], 16;" :: "r"(saddr), "l"(gsrc));
}

__device__ __forceinline__ unsigned packh2(float lo, float hi) {
    __half2 h = __floats2half2_rn(lo, hi);
    return *reinterpret_cast<unsigned*>(&h);
}

__global__ void pack_w2(const float* __restrict__ W2, const float* __restrict__ b2) {
    const int i = blockIdx.x * 256 + threadIdx.x;
    if (i >= 80 * 72 * 64) return;
    const int n  = i & 63;
    const int kp = (i >> 6) % 72;
    const int d  = i / (72 * 64);
    const int col = d * 64 + n;
    const int k0 = 2 * kp, k1 = 2 * kp + 1;
    const float lo = (k0 < 128) ? W2[(size_t)k0 * 5120 + col] : (k0 == 128 ? b2[col] : 0.f);
    const float hi = (k1 < 128) ? W2[(size_t)k1 * 5120 + col] : (k1 == 128 ? b2[col] : 0.f);
    w2h[(size_t)d * 4608 + kp * 64 + n] = packh2(lo, hi);
}

__global__ __launch_bounds__(384, 1)
void edge_kernel(const float* __restrict__ res,
                 const float* __restrict__ xf,
                 const float* __restrict__ esh,
                 const float* __restrict__ W1,
                 const float* __restrict__ b1,
                 const float* __restrict__ gamma,
                 const float* __restrict__ beta,
                 const int* __restrict__ ei,
                 float* __restrict__ out,
                 int E)
{
    extern __shared__ float smem[];
    unsigned* APu = (unsigned*)smem;            // k-pair-packed fp16 H
    unsigned* BPu = (unsigned*)smem + BP_W;     // 4 W2-chunk buffers
    unsigned* W1h = BPu + 2 * BP_BUF;           // aliased into ring bufs 2,3
    unsigned* Xp  = W1h + 32 * W1H_STR;         // 4352 u32 later
    float*    fs  = smem + FS_W;
    float*    b1s = smem + B1_W;
    float*    gs  = smem + GB_W;
    float*    bs  = gs + 64;

    const int tid  = threadIdx.x;
    const int lane = tid & 31;
    const int w    = tid >> 5;        // warp 0..11
    const int mg   = w & 3;           // m-group (32 rows)
    const int kt   = w >> 2;          // k-split third (0,1,2)
    const int g    = lane >> 2;
    const int q    = lane & 3;
    const int e0   = blockIdx.x * 128;

    // ---- kick off first two W2-chunk prefetches immediately ----------------
    auto prefetch = [&](int d) {
        unsigned* dstb = BPu + (d & 3) * BP_BUF;
        const unsigned* src = w2h + (size_t)d * 4608;
        #pragma unroll
        for (int c = tid; c < 1152; c += 384) {
            const int kp = c >> 4, seg = c & 15;
            cp_async16(dstb + kp * BP_STR + seg * 4, src + c * 4);
        }
        asm volatile("cp.async.commit_group;");
    };
    prefetch(0);
    prefetch(1);

    // ---- pack W1 -> W1h (k-pair fp16), X -> Xp ------------------------------
    for (int idx = tid; idx < 4096; idx += 384) {
        const int kp = idx >> 7, n = idx & 127;
        W1h[kp * W1H_STR + n] = packh2(W1[(size_t)(2 * kp) * 128 + n],
                                       W1[(size_t)(2 * kp + 1) * 128 + n]);
    }
    for (int idx = tid; idx < 4096; idx += 384) {
        const int row = idx >> 5, kp = idx & 31;
        const float2 v = *(const float2*)(xf + (size_t)(e0 + row) * 64 + 2 * kp);
        Xp[row * XP_STR + kp] = packh2(v.x, v.y);
    }
    if (tid < 128) b1s[tid] = b1[tid];
    if (tid < 64) { gs[tid] = gamma[tid]; bs[tid] = beta[tid]; }

    // ---- feats gather (one edge per thread, tid<128) -----------------------
    if (tid < 128) {
        const int e  = e0 + tid;
        const int di = ei[e];
        const int si = ei[E + e];
        const float* sr = res + (size_t)si * 56;
        const float* dr = res + (size_t)di * 56;
        const float s0 = esh[e * 4 + 0];
        const float sx = esh[e * 4 + 1];
        const float sy = esh[e * 4 + 2];
        const float sz = esh[e * 4 + 3];
        float* fr = fs + tid * F_STR;
        #pragma unroll
        for (int j = 0; j < 32; j++) { fr[j] = sr[j] * s0; fr[32 + j] = dr[j] * s0; }
        const float inv3 = 0.57735026918962576f;   // 1/sqrt(3)
        #pragma unroll
        for (int m = 0; m < 8; m++) {
            fr[64 + m] = (sr[32 + 3*m] * sx + sr[33 + 3*m] * sy + sr[34 + 3*m] * sz) * inv3;
            fr[72 + m] = (dr[32 + 3*m] * sx + dr[33 + 3*m] * sy + dr[34 + 3*m] * sz) * inv3;
        }
    }
    __syncthreads();

    // ---- phase 1: H = relu(X @ W1 + b1) via MMA, pack into APu -------------
    if (w < 8) {
        const int mg2 = w & 3, nh = w >> 2;
        float Gp[2][8][4];
        #pragma unroll
        for (int ks = 0; ks < 4; ks++) {
            unsigned pa[2][4];
            #pragma unroll
            for (int mt = 0; mt < 2; mt++) {
                const int r0 = mg2 * 32 + mt * 16;
                pa[mt][0] = Xp[(r0 + g)     * XP_STR + ks * 8 + q];
                pa[mt][1] = Xp[(r0 + 8 + g) * XP_STR + ks * 8 + q];
                pa[mt][2] = Xp[(r0 + g)     * XP_STR + ks * 8 + 4 + q];
                pa[mt][3] = Xp[(r0 + 8 + g) * XP_STR + ks * 8 + 4 + q];
            }
            #pragma unroll
            for (int nt = 0; nt < 8; nt++) {
                const int n = nh * 64 + nt * 8 + g;
                const unsigned b0 = W1h[(ks * 8 + q)     * W1H_STR + n];
                const unsigned b1v = W1h[(ks * 8 + 4 + q) * W1H_STR + n];
                if (ks == 0) {
                    mma_f16_z(Gp[0][nt], pa[0], b0, b1v);
                    mma_f16_z(Gp[1][nt], pa[1], b0, b1v);
                } else {
                    mma_f16(Gp[0][nt], pa[0], b0, b1v);
                    mma_f16(Gp[1][nt], pa[1], b0, b1v);
                }
            }
        }
        #pragma unroll
        for (int mt = 0; mt < 2; mt++) {
            const int r0 = mg2 * 32 + mt * 16;
            #pragma unroll
            for (int nt = 0; nt < 8; nt++) {
                const int col = nh * 64 + nt * 8 + 2 * q;
                const int kp  = nh * 32 + nt * 4 + q;
                const float bl = b1s[col], bh = b1s[col + 1];
                APu[(r0 + g) * AP_STR + kp] =
                    packh2(fmaxf(Gp[mt][nt][0] + bl, 0.f),
                           fmaxf(Gp[mt][nt][1] + bh, 0.f));
                APu[(r0 + 8 + g) * AP_STR + kp] =
                    packh2(fmaxf(Gp[mt][nt][2] + bl, 0.f),
                           fmaxf(Gp[mt][nt][3] + bh, 0.f));
            }
        }
    }
    if (tid < 128) {     // augmented cols: kp64 = (1,0) for b2 row; kp65..71 = 0
        APu[tid * AP_STR + 64] = 0x00003C00u;
        #pragma unroll
        for (int kp = 65; kp < 72; kp++) APu[tid * AP_STR + kp] = 0u;
    }
    __syncthreads();

    // ---- load persistent A fragments (H, unscaled) -------------------------
    const int rb0 = mg * 32;
    unsigned afr[2][3][4];
    #pragma unroll
    for (int mt = 0; mt < 2; mt++)
        #pragma unroll
        for (int ks = 0; ks < 3; ks++) {
            const int K8 = (kt * 3 + ks) * 8;
            const int r0 = rb0 + mt * 16;
            afr[mt][ks][0] = APu[(r0 + g)     * AP_STR + K8 + q];
            afr[mt][ks][1] = APu[(r0 + 8 + g) * AP_STR + K8 + q];
            afr[mt][ks][2] = APu[(r0 + g)     * AP_STR + K8 + 4 + q];
            afr[mt][ks][3] = APu[(r0 + 8 + g) * AP_STR + K8 + 4 + q];
        }

    float acc[2][8][4];
    #pragma unroll
    for (int mt = 0; mt < 2; mt++)
        #pragma unroll
        for (int nt = 0; nt < 8; nt++)
            #pragma unroll
            for (int i = 0; i < 4; i++) acc[mt][nt][i] = 0.f;

    const int rowA0 = rb0 + g;

    // ---- main loop: 80 d-chunks, one __syncthreads each --------------------
    #pragma unroll 1
    for (int d = 0; d < 80; d++) {
        if (d < 78) {
            prefetch(d + 2);
            asm volatile("cp.async.wait_group 2;");
        } else if (d == 78) {
            asm volatile("cp.async.wait_group 1;");
        } else {
            asm volatile("cp.async.wait_group 0;");
        }
        __syncthreads();

        const unsigned* Bb = BPu + (d & 3) * BP_BUF;
        const float f00 = fs[(rowA0)      * F_STR + d];
        const float f01 = fs[(rowA0 + 8)  * F_STR + d];
        const float f10 = fs[(rowA0 + 16) * F_STR + d];
        const float f11 = fs[(rowA0 + 24) * F_STR + d];

        #pragma unroll
        for (int nt = 0; nt < 8; nt++) {
            const int n = nt * 8 + g;
            float G0[4], G1[4];
            {
                const unsigned b0 = Bb[(kt * 24 + q)     * BP_STR + n];
                const unsigned b1 = Bb[(kt * 24 + 4 + q) * BP_STR + n];
                mma_f16_z(G0, afr[0][0], b0, b1);
                mma_f16_z(G1, afr[1][0], b0, b1);
            }
            {
                const unsigned b0 = Bb[(kt * 24 + 8 + q)  * BP_STR + n];
                const unsigned b1 = Bb[(kt * 24 + 12 + q) * BP_STR + n];
                mma_f16(G0, afr[0][1], b0, b1);
                mma_f16(G1, afr[1][1], b0, b1);
            }
            {
                const unsigned b0 = Bb[(kt * 24 + 16 + q) * BP_STR + n];
                const unsigned b1 = Bb[(kt * 24 + 20 + q) * BP_STR + n];
                mma_f16(G0, afr[0][2], b0, b1);
                mma_f16(G1, afr[1][2], b0, b1);
            }
            acc[0][nt][0] = fmaf(f00, G0[0], acc[0][nt][0]);
            acc[0][nt][1] = fmaf(f00, G0[1], acc[0][nt][1]);
            acc[0][nt][2] = fmaf(f01, G0[2], acc[0][nt][2]);
            acc[0][nt][3] = fmaf(f01, G0[3], acc[0][nt][3]);
            acc[1][nt][0] = fmaf(f10, G1[0], acc[1][nt][0]);
            acc[1][nt][1] = fmaf(f10, G1[1], acc[1][nt][1]);
            acc[1][nt][2] = fmaf(f11, G1[2], acc[1][nt][2]);
            acc[1][nt][3] = fmaf(f11, G1[3], acc[1][nt][3]);
        }
    }
    __syncthreads();

    // ---- cross-warp (3-way k-split) reduction ------------------------------
    float* red = (float*)BPu;                    // chunk buffers dead
    if (kt >= 1) {
        float* dst = red + (kt - 1) * 8192 + mg * 2048;
        #pragma unroll
        for (int mt = 0; mt < 2; mt++)
            #pragma unroll
            for (int nt = 0; nt < 8; nt++)
                #pragma unroll
                for (int i = 0; i < 4; i++)
                    dst[(mt * 32 + nt * 4 + i) * 32 + lane] = acc[mt][nt][i];
    }
    __syncthreads();
    if (kt == 0) {
        const float* s1 = red + mg * 2048;
        const float* s2 = red + 8192 + mg * 2048;
        #pragma unroll
        for (int mt = 0; mt < 2; mt++)
            #pragma unroll
            for (int nt = 0; nt < 8; nt++)
                #pragma unroll
                for (int i = 0; i < 4; i++) {
                    const int off = (mt * 32 + nt * 4 + i) * 32 + lane;
                    acc[mt][nt][i] += s1[off] + s2[off];
                }

        // ---- epilogue: residual + LayerNorm --------------------------------
        const float inv_s80 = 0.111803398874989485f;   // 1/sqrt(80)
        #pragma unroll
        for (int mt = 0; mt < 2; mt++) {
            #pragma unroll
            for (int par = 0; par < 2; par++) {
                const int r = rowA0 + mt * 16 + par * 8;
                const size_t rg = (size_t)(e0 + r);
                const float* xrow = xf + rg * 64;
                float v[16];
                float s = 0.f, ss = 0.f;
                #pragma unroll
                for (int nt = 0; nt < 8; nt++) {
                    const int h = nt * 8 + 2 * q;
                    const float2 xv = *(const float2*)(xrow + h);
                    const float v0 = acc[mt][nt][par * 2 + 0] * inv_s80 + xv.x;
                    const float v1 = acc[mt][nt][par * 2 + 1] * inv_s80 + xv.y;
                    v[nt * 2] = v0; v[nt * 2 + 1] = v1;
                    s += v0 + v1;
                    ss += v0 * v0 + v1 * v1;
                }
                s  += __shfl_xor_sync(0xffffffffu, s, 1);
                s  += __shfl_xor_sync(0xffffffffu, s, 2);
                ss += __shfl_xor_sync(0xffffffffu, ss, 1);
                ss += __shfl_xor_sync(0xffffffffu, ss, 2);
                const float mean = s * (1.f / 64.f);
                const float var  = ss * (1.f / 64.f) - mean * mean;
                const float rstd = rsqrtf(var + 1e-5f);
                float* orow = out + rg * 64;
                #pragma unroll
                for (int nt = 0; nt < 8; nt++) {
                    const int h = nt * 8 + 2 * q;
                    float2 o;
                    o.x = (v[nt * 2]     - mean) * rstd * gs[h]     + bs[h];
                    o.y = (v[nt * 2 + 1] - mean) * rstd * gs[h + 1] + bs[h + 1];
                    *(float2*)(orow + h) = o;
                }
            }
        }
    }
}

extern "C" void kernel_launch(void* const* d_in, const int* in_sizes, int n_in,
                              void* d_out, int out_size)
{
    const float* res   = (const float*)d_in[0];
    const float* xf    = (const float*)d_in[1];
    const float* esh   = (const float*)d_in[2];
    const float* W1    = (const float*)d_in[3];
    const float* b1    = (const float*)d_in[4];
    const float* W2    = (const float*)d_in[5];
    const float* b2    = (const float*)d_in[6];
    const float* gamma = (const float*)d_in[7];
    const float* beta  = (const float*)d_in[8];
    const int*   ei    = (const int*)d_in[9];   // int32: JAX x64-disabled

    const int E = in_sizes[1] / 64;             // edge_features is (E, 64)
    const size_t smem_bytes = SMEM_W * sizeof(float);

    cudaFuncSetAttribute(edge_kernel, cudaFuncAttributeMaxDynamicSharedMemorySize,
                         (int)smem_bytes);

    pack_w2<<<(80 * 72 * 64 + 255) / 256, 256>>>(W2, b2);
    edge_kernel<<<E / 128, 384, smem_bytes>>>(res, xf, esh, W1, b1,
                                              gamma, beta, ei, (float*)d_out, E);
}

// round 12
// speedup vs baseline: 2.1417x; 1.0406x over previous
#include <cuda_runtime.h>
#include <cuda_fp16.h>
#include <cstdint>

// ---------------------------------------------------------------------------
// EdgeUpdate, R11.
//   fp16 mma.sync m16n8k16 everywhere.  384 threads: 4 m-groups x 3-way
//   k-split.  NEW: per-k-group B prefetch + named barriers (bar.sync 1+kt,128)
//   -- the three k-groups run fully decoupled through the 80-chunk main loop
//   (no global __syncthreads per d).  feats pre-scaled by 1/sqrt(80).
// ---------------------------------------------------------------------------

constexpr int AP_STR  = 76;                 // APu: 128 x 76 u32 (kp 0..71)
constexpr int BP_W    = 9728;               // u32 offset of B ring
constexpr int BP_BUF  = 5184;               // 72*72 u32 per buffer
constexpr int BP_STR  = 72;
constexpr int W1H_STR = 136;                // w1h row stride (conflict-free)
constexpr int XP_STR  = 36;                 // Xp row stride (conflict-free)
constexpr int FS_W    = 30464;  constexpr int F_STR = 81;   // 128 x 81 floats
constexpr int B1_W    = 40832;
constexpr int GB_W    = 40960;
constexpr int SMEM_W  = 41088;              // 164352 bytes

// k-pair-packed fp16 W2aug chunks: w2h[d][kp][n], kp=0..71 (k=2kp,2kp+1)
__device__ unsigned w2h[80 * 72 * 64];

__device__ __forceinline__ void mma_f16(float* c, const unsigned* a,
                                        unsigned b0, unsigned b1) {
    asm volatile(
        "mma.sync.aligned.m16n8k16.row.col.f32.f16.f16.f32 "
        "{%0,%1,%2,%3}, {%4,%5,%6,%7}, {%8,%9}, {%0,%1,%2,%3};"
        : "+f"(c[0]), "+f"(c[1]), "+f"(c[2]), "+f"(c[3])
        : "r"(a[0]), "r"(a[1]), "r"(a[2]), "r"(a[3]), "r"(b0), "r"(b1));
}

__device__ __forceinline__ void mma_f16_z(float* d, const unsigned* a,
                                          unsigned b0, unsigned b1) {
    asm volatile(
        "mma.sync.aligned.m16n8k16.row.col.f32.f16.f16.f32 "
        "{%0,%1,%2,%3}, {%4,%5,%6,%7}, {%8,%9}, {%10,%11,%12,%13};"
        : "=f"(d[0]), "=f"(d[1]), "=f"(d[2]), "=f"(d[3])
        : "r"(a[0]), "r"(a[1]), "r"(a[2]), "r"(a[3]), "r"(b0), "r"(b1),
          "f"(0.f), "f"(0.f), "f"(0.f), "f"(0.f));
}

__device__ __forceinline__ void cp_async16(void* smem_dst, const void* gsrc) {
    unsigned saddr = (unsigned)__cvta_generic_to_shared(smem_dst);
    asm volatile("cp.async.cg.shared.global [%0], [%1], 16;" :: "r"(saddr), "l"(gsrc));
}

__device__ __forceinline__ unsigned packh2(float lo, float hi) {
    __half2 h = __floats2half2_rn(lo, hi);
    return *reinterpret_cast<unsigned*>(&h);
}

__global__ void pack_w2(const float* __restrict__ W2, const float* __restrict__ b2) {
    const int i = blockIdx.x * 256 + threadIdx.x;
    if (i >= 80 * 72 * 64) return;
    const int n  = i & 63;
    const int kp = (i >> 6) % 72;
    const int d  = i / (72 * 64);
    const int col = d * 64 + n;
    const int k0 = 2 * kp, k1 = 2 * kp + 1;
    const float lo = (k0 < 128) ? W2[(size_t)k0 * 5120 + col] : (k0 == 128 ? b2[col] : 0.f);
    const float hi = (k1 < 128) ? W2[(size_t)k1 * 5120 + col] : (k1 == 128 ? b2[col] : 0.f);
    w2h[(size_t)d * 4608 + kp * 64 + n] = packh2(lo, hi);
}

__global__ __launch_bounds__(384, 1)
void edge_kernel(const float* __restrict__ res,
                 const float* __restrict__ xf,
                 const float* __restrict__ esh,
                 const float* __restrict__ W1,
                 const float* __restrict__ b1,
                 const float* __restrict__ gamma,
                 const float* __restrict__ beta,
                 const int* __restrict__ ei,
                 float* __restrict__ out,
                 int E)
{
    extern __shared__ float smem[];
    unsigned* APu = (unsigned*)smem;            // k-pair-packed fp16 H
    unsigned* BPu = (unsigned*)smem + BP_W;     // 4 W2-chunk buffers
    unsigned* W1h = BPu + 2 * BP_BUF;           // aliased into ring bufs 2,3
    unsigned* Xp  = W1h + 32 * W1H_STR;
    float*    fs  = smem + FS_W;
    float*    b1s = smem + B1_W;
    float*    gs  = smem + GB_W;
    float*    bs  = gs + 64;

    const int tid  = threadIdx.x;
    const int lane = tid & 31;
    const int w    = tid >> 5;        // warp 0..11
    const int mg   = w & 3;           // m-group (32 rows)
    const int kt   = w >> 2;          // k-split third (0,1,2)
    const int g    = lane >> 2;
    const int q    = lane & 3;
    const int e0   = blockIdx.x * 128;

    // ---- group-local prefetch: group kt owns B rows [24kt, 24kt+24) --------
    auto prefetch = [&](int d) {
        unsigned* dstb = BPu + (d & 3) * BP_BUF + kt * 24 * BP_STR;
        const unsigned* src = w2h + (size_t)d * 4608 + kt * 24 * 64;
        const int tg = tid & 127;
        #pragma unroll
        for (int t = tg; t < 384; t += 128) {            // 24 rows x 16 segs
            const int row = t >> 4, seg = t & 15;
            cp_async16(dstb + row * BP_STR + seg * 4, src + row * 64 + seg * 4);
        }
        asm volatile("cp.async.commit_group;");
    };
    prefetch(0);
    prefetch(1);

    // ---- pack W1 -> W1h (k-pair fp16), X -> Xp ------------------------------
    for (int idx = tid; idx < 4096; idx += 384) {
        const int kp = idx >> 7, n = idx & 127;
        W1h[kp * W1H_STR + n] = packh2(W1[(size_t)(2 * kp) * 128 + n],
                                       W1[(size_t)(2 * kp + 1) * 128 + n]);
    }
    for (int idx = tid; idx < 4096; idx += 384) {
        const int row = idx >> 5, kp = idx & 31;
        const float2 v = *(const float2*)(xf + (size_t)(e0 + row) * 64 + 2 * kp);
        Xp[row * XP_STR + kp] = packh2(v.x, v.y);
    }
    if (tid < 128) b1s[tid] = b1[tid];
    if (tid < 64) { gs[tid] = gamma[tid]; bs[tid] = beta[tid]; }

    // ---- feats gather, pre-scaled by 1/sqrt(80) ----------------------------
    if (tid < 128) {
        const int e  = e0 + tid;
        const int di = ei[e];
        const int si = ei[E + e];
        const float* sr = res + (size_t)si * 56;
        const float* dr = res + (size_t)di * 56;
        const float inv80 = 0.111803398874989485f;            // 1/sqrt(80)
        const float i380  = 0.111803398874989485f * 0.57735026918962576f;
        const float s0 = esh[e * 4 + 0] * inv80;
        const float sx = esh[e * 4 + 1] * i380;
        const float sy = esh[e * 4 + 2] * i380;
        const float sz = esh[e * 4 + 3] * i380;
        float* fr = fs + tid * F_STR;
        #pragma unroll
        for (int j = 0; j < 32; j++) { fr[j] = sr[j] * s0; fr[32 + j] = dr[j] * s0; }
        #pragma unroll
        for (int m = 0; m < 8; m++) {
            fr[64 + m] = sr[32 + 3*m] * sx + sr[33 + 3*m] * sy + sr[34 + 3*m] * sz;
            fr[72 + m] = dr[32 + 3*m] * sx + dr[33 + 3*m] * sy + dr[34 + 3*m] * sz;
        }
    }
    __syncthreads();

    // ---- phase 1: H = relu(X @ W1 + b1) via MMA, pack into APu -------------
    if (w < 8) {
        const int mg2 = w & 3, nh = w >> 2;
        float Gp[2][8][4];
        #pragma unroll
        for (int ks = 0; ks < 4; ks++) {
            unsigned pa[2][4];
            #pragma unroll
            for (int mt = 0; mt < 2; mt++) {
                const int r0 = mg2 * 32 + mt * 16;
                pa[mt][0] = Xp[(r0 + g)     * XP_STR + ks * 8 + q];
                pa[mt][1] = Xp[(r0 + 8 + g) * XP_STR + ks * 8 + q];
                pa[mt][2] = Xp[(r0 + g)     * XP_STR + ks * 8 + 4 + q];
                pa[mt][3] = Xp[(r0 + 8 + g) * XP_STR + ks * 8 + 4 + q];
            }
            #pragma unroll
            for (int nt = 0; nt < 8; nt++) {
                const int n = nh * 64 + nt * 8 + g;
                const unsigned b0 = W1h[(ks * 8 + q)     * W1H_STR + n];
                const unsigned b1v = W1h[(ks * 8 + 4 + q) * W1H_STR + n];
                if (ks == 0) {
                    mma_f16_z(Gp[0][nt], pa[0], b0, b1v);
                    mma_f16_z(Gp[1][nt], pa[1], b0, b1v);
                } else {
                    mma_f16(Gp[0][nt], pa[0], b0, b1v);
                    mma_f16(Gp[1][nt], pa[1], b0, b1v);
                }
            }
        }
        #pragma unroll
        for (int mt = 0; mt < 2; mt++) {
            const int r0 = mg2 * 32 + mt * 16;
            #pragma unroll
            for (int nt = 0; nt < 8; nt++) {
                const int col = nh * 64 + nt * 8 + 2 * q;
                const int kp  = nh * 32 + nt * 4 + q;
                const float bl = b1s[col], bh = b1s[col + 1];
                APu[(r0 + g) * AP_STR + kp] =
                    packh2(fmaxf(Gp[mt][nt][0] + bl, 0.f),
                           fmaxf(Gp[mt][nt][1] + bh, 0.f));
                APu[(r0 + 8 + g) * AP_STR + kp] =
                    packh2(fmaxf(Gp[mt][nt][2] + bl, 0.f),
                           fmaxf(Gp[mt][nt][3] + bh, 0.f));
            }
        }
    }
    if (tid < 128) {     // augmented cols: kp64 = (1,0) for b2 row; kp65..71 = 0
        APu[tid * AP_STR + 64] = 0x00003C00u;
        #pragma unroll
        for (int kp = 65; kp < 72; kp++) APu[tid * AP_STR + kp] = 0u;
    }
    __syncthreads();

    // ---- load persistent A fragments (H, unscaled) -------------------------
    const int rb0 = mg * 32;
    unsigned afr[2][3][4];
    #pragma unroll
    for (int mt = 0; mt < 2; mt++)
        #pragma unroll
        for (int ks = 0; ks < 3; ks++) {
            const int K8 = (kt * 3 + ks) * 8;
            const int r0 = rb0 + mt * 16;
            afr[mt][ks][0] = APu[(r0 + g)     * AP_STR + K8 + q];
            afr[mt][ks][1] = APu[(r0 + 8 + g) * AP_STR + K8 + q];
            afr[mt][ks][2] = APu[(r0 + g)     * AP_STR + K8 + 4 + q];
            afr[mt][ks][3] = APu[(r0 + 8 + g) * AP_STR + K8 + 4 + q];
        }

    float acc[2][8][4];
    #pragma unroll
    for (int mt = 0; mt < 2; mt++)
        #pragma unroll
        for (int nt = 0; nt < 8; nt++)
            #pragma unroll
            for (int i = 0; i < 4; i++) acc[mt][nt][i] = 0.f;

    const int rowA0 = rb0 + g;
    const int barid = 1 + kt;

    // ---- main loop: 80 d-chunks; per-group named barrier only --------------
    #pragma unroll 1
    for (int d = 0; d < 80; d++) {
        if (d < 78) {
            prefetch(d + 2);
            asm volatile("cp.async.wait_group 2;");
        } else if (d == 78) {
            asm volatile("cp.async.wait_group 1;");
        } else {
            asm volatile("cp.async.wait_group 0;");
        }
        asm volatile("bar.sync %0, %1;" :: "r"(barid), "r"(128) : "memory");

        const unsigned* Bb = BPu + (d & 3) * BP_BUF;
        const float f00 = fs[(rowA0)      * F_STR + d];
        const float f01 = fs[(rowA0 + 8)  * F_STR + d];
        const float f10 = fs[(rowA0 + 16) * F_STR + d];
        const float f11 = fs[(rowA0 + 24) * F_STR + d];

        #pragma unroll
        for (int nt = 0; nt < 8; nt++) {
            const int n = nt * 8 + g;
            float G0[4], G1[4];
            {
                const unsigned b0 = Bb[(kt * 24 + q)     * BP_STR + n];
                const unsigned b1 = Bb[(kt * 24 + 4 + q) * BP_STR + n];
                mma_f16_z(G0, afr[0][0], b0, b1);
                mma_f16_z(G1, afr[1][0], b0, b1);
            }
            {
                const unsigned b0 = Bb[(kt * 24 + 8 + q)  * BP_STR + n];
                const unsigned b1 = Bb[(kt * 24 + 12 + q) * BP_STR + n];
                mma_f16(G0, afr[0][1], b0, b1);
                mma_f16(G1, afr[1][1], b0, b1);
            }
            {
                const unsigned b0 = Bb[(kt * 24 + 16 + q) * BP_STR + n];
                const unsigned b1 = Bb[(kt * 24 + 20 + q) * BP_STR + n];
                mma_f16(G0, afr[0][2], b0, b1);
                mma_f16(G1, afr[1][2], b0, b1);
            }
            acc[0][nt][0] = fmaf(f00, G0[0], acc[0][nt][0]);
            acc[0][nt][1] = fmaf(f00, G0[1], acc[0][nt][1]);
            acc[0][nt][2] = fmaf(f01, G0[2], acc[0][nt][2]);
            acc[0][nt][3] = fmaf(f01, G0[3], acc[0][nt][3]);
            acc[1][nt][0] = fmaf(f10, G1[0], acc[1][nt][0]);
            acc[1][nt][1] = fmaf(f10, G1[1], acc[1][nt][1]);
            acc[1][nt][2] = fmaf(f11, G1[2], acc[1][nt][2]);
            acc[1][nt][3] = fmaf(f11, G1[3], acc[1][nt][3]);
        }
    }
    __syncthreads();

    // ---- cross-warp (3-way k-split) reduction ------------------------------
    float* red = (float*)BPu;                    // chunk buffers dead
    if (kt >= 1) {
        float* dst = red + (kt - 1) * 8192 + mg * 2048;
        #pragma unroll
        for (int mt = 0; mt < 2; mt++)
            #pragma unroll
            for (int nt = 0; nt < 8; nt++)
                #pragma unroll
                for (int i = 0; i < 4; i++)
                    dst[(mt * 32 + nt * 4 + i) * 32 + lane] = acc[mt][nt][i];
    }
    __syncthreads();
    if (kt == 0) {
        const float* s1 = red + mg * 2048;
        const float* s2 = red + 8192 + mg * 2048;
        #pragma unroll
        for (int mt = 0; mt < 2; mt++)
            #pragma unroll
            for (int nt = 0; nt < 8; nt++)
                #pragma unroll
                for (int i = 0; i < 4; i++) {
                    const int off = (mt * 32 + nt * 4 + i) * 32 + lane;
                    acc[mt][nt][i] += s1[off] + s2[off];
                }

        // ---- epilogue: residual + LayerNorm (feats pre-scaled) -------------
        #pragma unroll
        for (int mt = 0; mt < 2; mt++) {
            #pragma unroll
            for (int par = 0; par < 2; par++) {
                const int r = rowA0 + mt * 16 + par * 8;
                const size_t rg = (size_t)(e0 + r);
                const float* xrow = xf + rg * 64;
                float v[16];
                float s = 0.f, ss = 0.f;
                #pragma unroll
                for (int nt = 0; nt < 8; nt++) {
                    const int h = nt * 8 + 2 * q;
                    const float2 xv = *(const float2*)(xrow + h);
                    const float v0 = acc[mt][nt][par * 2 + 0] + xv.x;
                    const float v1 = acc[mt][nt][par * 2 + 1] + xv.y;
                    v[nt * 2] = v0; v[nt * 2 + 1] = v1;
                    s += v0 + v1;
                    ss += v0 * v0 + v1 * v1;
                }
                s  += __shfl_xor_sync(0xffffffffu, s, 1);
                s  += __shfl_xor_sync(0xffffffffu, s, 2);
                ss += __shfl_xor_sync(0xffffffffu, ss, 1);
                ss += __shfl_xor_sync(0xffffffffu, ss, 2);
                const float mean = s * (1.f / 64.f);
                const float var  = ss * (1.f / 64.f) - mean * mean;
                const float rstd = rsqrtf(var + 1e-5f);
                float* orow = out + rg * 64;
                #pragma unroll
                for (int nt = 0; nt < 8; nt++) {
                    const int h = nt * 8 + 2 * q;
                    float2 o;
                    o.x = (v[nt * 2]     - mean) * rstd * gs[h]     + bs[h];
                    o.y = (v[nt * 2 + 1] - mean) * rstd * gs[h + 1] + bs[h + 1];
                    *(float2*)(orow + h) = o;
                }
            }
        }
    }
}

extern "C" void kernel_launch(void* const* d_in, const int* in_sizes, int n_in,
                              void* d_out, int out_size)
{
    const float* res   = (const float*)d_in[0];
    const float* xf    = (const float*)d_in[1];
    const float* esh   = (const float*)d_in[2];
    const float* W1    = (const float*)d_in[3];
    const float* b1    = (const float*)d_in[4];
    const float* W2    = (const float*)d_in[5];
    const float* b2    = (const float*)d_in[6];
    const float* gamma = (const float*)d_in[7];
    const float* beta  = (const float*)d_in[8];
    const int*   ei    = (const int*)d_in[9];   // int32: JAX x64-disabled

    const int E = in_sizes[1] / 64;             // edge_features is (E, 64)
    const size_t smem_bytes = SMEM_W * sizeof(float);

    cudaFuncSetAttribute(edge_kernel, cudaFuncAttributeMaxDynamicSharedMemorySize,
                         (int)smem_bytes);

    pack_w2<<<(80 * 72 * 64 + 255) / 256, 256>>>(W2, b2);
    edge_kernel<<<E / 128, 384, smem_bytes>>>(res, xf, esh, W1, b1,
                                              gamma, beta, ei, (float*)d_out, E);
}